// round 14
// baseline (speedup 1.0000x reference)
#include <cuda_runtime.h>
#include <cuda_fp16.h>
#include <cstdint>
#include <math.h>

// ---------------------------------------------------------------------------
// Seq2Seq LSTM via mma.sync (HMMA fp16): B=256, T_in=512, F=64, H=512, T_out=64
// Round 14: denser warp tiles. 8 warps of 32x16 (2M x 4N slices of the 64x64
// CTA tile), 256 threads. Per ka: 2 A-LDSM + 1 B-LDSM + 4 MMA (A reuse), so
// SM-level LDSM drops 25% and per-warp loop bookkeeping halves. Same 128 CTAs,
// 12-stage quad ring, walking issue pointers, fast-math epilogue, fused proj.
// ---------------------------------------------------------------------------

using f16 = __half;

#define Bsz   256
#define Hd    512
#define Fin   64
#define T_IN  512
#define T_OUT 64
#define N4    2048
#define BH    (Bsz*Hd)
#define NBLK  128
#define THR   256

// per-stage smem: A 8K | B 8K
#define OFF_B  8192
#define BUFB   16384
#define NSTAGE 12
#define DSMEM  (NSTAGE*BUFB + 1024)

// ------------------------- device scratch (static) -------------------------
__device__ __align__(16) f16 g_xc[(size_t)T_IN * Bsz * Fin];
__device__ __align__(16) f16 g_hs[(size_t)T_IN * BH];
__device__ __align__(16) f16 g_h1[2][BH];
__device__ __align__(16) f16 g_d0[2][BH];
__device__ __align__(16) f16 g_d1[2][BH];
__device__ float g_pacc[2][Bsz];          // proj ping-pong accumulators

// weights, remapped rows (see remap_row), layout [2048][K] fp16
__device__ __align__(16) f16 gB_x0[N4 * Fin];
__device__ __align__(16) f16 gB_h0[N4 * Hd];
__device__ __align__(16) f16 gB_x1[N4 * Hd];
__device__ __align__(16) f16 gB_h1[N4 * Hd];
__device__ __align__(16) f16 gB_d0[N4 * Hd];
__device__ __align__(16) f16 gB_x1d[N4 * Hd];
__device__ __align__(16) f16 gB_d1[N4 * Hd];

__device__ __align__(16) float g_b0[N4], g_b1[N4], g_bd0[N4], g_bd1[N4], g_Wv[N4];

__device__ unsigned g_cnt;
__device__ volatile unsigned g_gen;

// ------------------------------- asm helpers -------------------------------
#define LDSM4(R, A) \
    asm volatile("ldmatrix.sync.aligned.m8n8.x4.shared.b16 {%0,%1,%2,%3}, [%4];" \
        : "=r"((R)[0]), "=r"((R)[1]), "=r"((R)[2]), "=r"((R)[3]) : "r"(A))

#define MMA(D, A, B) \
    asm volatile("mma.sync.aligned.m16n8k16.row.col.f32.f16.f16.f32 " \
        "{%0,%1,%2,%3}, {%4,%5,%6,%7}, {%8,%9}, {%0,%1,%2,%3};" \
        : "+f"((D)[0]), "+f"((D)[1]), "+f"((D)[2]), "+f"((D)[3]) \
        : "r"((A)[0]), "r"((A)[1]), "r"((A)[2]), "r"((A)[3]), \
          "r"((B)[0]), "r"((B)[1]))

#define CP16(sa, ga) \
    asm volatile("cp.async.cg.shared.global [%0], [%1], 16;" :: "r"(sa), "l"(ga))
#define CP_COMMIT() asm volatile("cp.async.commit_group;")
#define CP_WAIT0()  asm volatile("cp.async.wait_group 0;" ::: "memory")
#define CP_WAIT1()  asm volatile("cp.async.wait_group 1;" ::: "memory")

__device__ __forceinline__ uint32_t smem_u32(const void* p) {
    uint32_t a;
    asm("{ .reg .u64 t; cvta.to.shared.u64 t, %1; cvt.u32.u64 %0, t; }"
        : "=r"(a) : "l"(p));
    return a;
}

// Fast activations: MUFU-based. |err| ~2^-21, far below fp16 gate noise.
__device__ __forceinline__ float sigf(float x) {
    return __fdividef(1.0f, 1.0f + __expf(-x));
}
__device__ __forceinline__ float tanhf_fast(float x) {
    return 1.0f - __fdividef(2.0f, __expf(2.0f * x) + 1.0f);
}

__device__ __forceinline__ void grid_sync() {
    __syncthreads();
    if (threadIdx.x == 0) {
        __threadfence();
        unsigned g = g_gen;
        unsigned old = atomicAdd(&g_cnt, 1u);
        if (old == NBLK - 1) {
            g_cnt = 0;
            __threadfence();
            g_gen = g + 1;
        } else {
            while (g_gen == g) __nanosleep(64);
            __threadfence();
        }
    }
    __syncthreads();
}

// ----------------------------- GEMM machinery ------------------------------
struct Seg {
    const f16 *A;   // A [row][K]
    const f16 *B;   // B' [2048][K]
    int K;          // 64 or 512
};

// Warp tile 32x16: per ka, A fragments a0 (rows +0..15) and a1 (+16..31),
// one B LDSM4 (16 cols). a1 address = a0 + 2048 (swizzle untouched by bit 11).
__device__ __forceinline__ void compute_chunk(uint32_t sbase, float acc[4][4],
                                              const uint32_t* asw,
                                              const uint32_t* bsw) {
#pragma unroll
    for (int ka = 0; ka < 4; ++ka) {
        uint32_t a0[4], a1[4], b[4];
        LDSM4(a0, sbase + asw[ka]);
        LDSM4(a1, sbase + asw[ka] + 2048);
        LDSM4(b, sbase + bsw[ka]);
        MMA(acc[0], a0, b);
        MMA(acc[1], a0, b + 2);
        MMA(acc[2], a1, b);
        MMA(acc[3], a1, b + 2);
    }
}

// 12-stage ring, QUAD groups: one wait + one syncthreads per 4 chunks.
// 256 threads: each issues 2 A-pieces + 2 B-pieces (4 CP16) per chunk.
__device__ __forceinline__ void pipe_gemm(uint32_t dsm32, const Seg* segs, int nseg,
                                          int split, float aA[4][4], float aB[4][4],
                                          int bm, int colb, int tid,
                                          const uint32_t* asw, const uint32_t* bsw) {
    int tot = 0;
#pragma unroll
    for (int i = 0; i < 4; ++i) if (i < nseg) tot += segs[i].K >> 6;
    const int G = (tot + 3) >> 2;

    const int u0 = tid * 2, u1 = tid * 2 + 1;
    const int rA0 = u0 >> 3, sA0 = (u0 & 7) * 8;
    const int rA1 = u1 >> 3, sA1 = (u1 & 7) * 8;
    const uint32_t sw0 = (uint32_t)((u0 * 16) ^ (((u0 * 16) >> 3) & 0x70));
    const uint32_t sw1 = (uint32_t)((u1 * 16) ^ (((u1 * 16) >> 3) & 0x70));
    const int ra512_0 = (bm + rA0) * 512 + sA0;
    const int ra512_1 = (bm + rA1) * 512 + sA1;
    const int rb512_0 = (colb + rA0) * 512 + sA0;
    const int rb512_1 = (colb + rA1) * 512 + sA1;

    // walking issue pointers; reseed at (rare) segment boundaries
    const f16 *pA0, *pA1, *pB0, *pB1;
    if (segs[0].K == 64) {
        pA0 = segs[0].A + (bm + rA0) * 64 + sA0;
        pA1 = segs[0].A + (bm + rA1) * 64 + sA1;
        pB0 = segs[0].B + (colb + rA0) * 64 + sA0;
        pB1 = segs[0].B + (colb + rA1) * 64 + sA1;
    } else {
        pA0 = segs[0].A + ra512_0;
        pA1 = segs[0].A + ra512_1;
        pB0 = segs[0].B + rb512_0;
        pB1 = segs[0].B + rb512_1;
    }
    int rem = segs[0].K >> 6;
    int si = 0;
    int issued = 0;
    uint32_t ibase = dsm32;
    const uint32_t wrap = dsm32 + NSTAGE * BUFB;

    auto issue1 = [&]() {
        CP16(ibase + sw0, pA0);
        CP16(ibase + sw1, pA1);
        CP16(ibase + OFF_B + sw0, pB0);
        CP16(ibase + OFF_B + sw1, pB1);
        ibase += BUFB;
        if (ibase == wrap) ibase = dsm32;
        ++issued;
        if (--rem == 0) {
            ++si;
            if (si == 1 && nseg > 1) {
                pA0 = segs[1].A + ra512_0; pA1 = segs[1].A + ra512_1;
                pB0 = segs[1].B + rb512_0; pB1 = segs[1].B + rb512_1;
                rem = segs[1].K >> 6;
            } else if (si == 2 && nseg > 2) {
                pA0 = segs[2].A + ra512_0; pA1 = segs[2].A + ra512_1;
                pB0 = segs[2].B + rb512_0; pB1 = segs[2].B + rb512_1;
                rem = segs[2].K >> 6;
            } else if (si == 3 && nseg > 3) {
                pA0 = segs[3].A + ra512_0; pA1 = segs[3].A + ra512_1;
                pB0 = segs[3].B + rb512_0; pB1 = segs[3].B + rb512_1;
                rem = segs[3].K >> 6;
            }
        } else {
            pA0 += 64; pA1 += 64; pB0 += 64; pB1 += 64;
        }
    };

    // prefill 2 groups
    {
        const int pre = G < 2 ? G : 2;
        for (int g = 0; g < pre; ++g) {
#pragma unroll
            for (int j = 0; j < 4; ++j) if (issued < tot) issue1();
            CP_COMMIT();
        }
    }

    uint32_t cbase = dsm32;
    int c = 0;
    for (int g = 0; g < G; ++g) {
        if (g + 1 < G) CP_WAIT1();
        else           CP_WAIT0();
        __syncthreads();
        if (g + 2 < G) {
#pragma unroll
            for (int j = 0; j < 4; ++j) if (issued < tot) issue1();
            CP_COMMIT();
        }
#pragma unroll
        for (int j = 0; j < 4; ++j) {
            if (c < tot) {
                compute_chunk(cbase, c < split ? aA : aB, asw, bsw);
                cbase += BUFB;
                if (cbase == wrap) cbase = dsm32;
                ++c;
            }
        }
    }
}

#define ZERO_ACC(A) \
    do { _Pragma("unroll") for (int _a = 0; _a < 4; ++_a) \
         _Pragma("unroll") for (int _d = 0; _d < 4; ++_d) (A)[_a][_d] = 0.0f; } while (0)

// Epilogue: thread owns 4 rows (mf in {0,1}, rr in {0,1}) x ONE unit.
// acc[mf*2+0][rr*2+p]: p=0 -> i, p=1 -> f; acc[mf*2+1]: p=0 -> g, p=1 -> o.
__device__ __forceinline__ void epilogue_lstm(float acc[4][4], float* c,
                                              const float* bias,
                                              const float* prevv, const float* Wv,
                                              f16* H,
                                              const float* pjW, float* pacc,
                                              int bm, int G16, int wm, int lane) {
    const int q = lane & 3, r = lane >> 2;
    const float2* b2 = (const float2*)bias;
    const float2 bIF = __ldg(&b2[G16 * 8 + q]);
    const float2 bGO = __ldg(&b2[G16 * 8 + 4 + q]);
    float2 wIF = make_float2(0.f, 0.f), wGO = make_float2(0.f, 0.f);
    if (Wv) {
        const float2* w2 = (const float2*)Wv;
        wIF = __ldg(&w2[G16 * 8 + q]);
        wGO = __ldg(&w2[G16 * 8 + 4 + q]);
    }
    const int u = G16 * 4 + q;      // original hidden-unit index
    float pw = 0.0f;
    if (pjW) pw = __ldg(&pjW[u]);
    float rsum[4] = {0.0f, 0.0f, 0.0f, 0.0f};
#pragma unroll
    for (int mf = 0; mf < 2; ++mf) {
#pragma unroll
        for (int rr = 0; rr < 2; ++rr) {
            const int m = bm + wm * 32 + mf * 16 + r + rr * 8;
            const int d = rr * 2;
            float gi = acc[mf * 2 + 0][d + 0] + bIF.x;
            float gf = acc[mf * 2 + 0][d + 1] + bIF.y;
            float gg = acc[mf * 2 + 1][d + 0] + bGO.x;
            float go = acc[mf * 2 + 1][d + 1] + bGO.y;
            if (prevv) {
                const float pv = prevv[m];
                gi = fmaf(pv, wIF.x, gi); gf = fmaf(pv, wIF.y, gf);
                gg = fmaf(pv, wGO.x, gg); go = fmaf(pv, wGO.y, go);
            }
            const int ci = mf * 2 + rr;
            float cn = sigf(gf) * c[ci] + sigf(gi) * tanhf_fast(gg);
            float hn = sigf(go) * tanhf_fast(cn);
            c[ci] = cn;
            if (pjW) rsum[ci] = hn * pw;
            H[(size_t)m * Hd + u] = __float2half(hn);
        }
    }
    if (pjW) {
#pragma unroll
        for (int i = 0; i < 4; ++i) {
            rsum[i] += __shfl_xor_sync(0xffffffffu, rsum[i], 1);
            rsum[i] += __shfl_xor_sync(0xffffffffu, rsum[i], 2);
        }
        if (q == 0) {
            const int mb = bm + wm * 32 + r;
            atomicAdd(&pacc[mb], rsum[0]);
            atomicAdd(&pacc[mb + 8], rsum[1]);
            atomicAdd(&pacc[mb + 16], rsum[2]);
            atomicAdd(&pacc[mb + 24], rsum[3]);
        }
    }
}

// ------------------------------- prep kernel -------------------------------
// gate g (0..3), unit j (0..511) -> col = 16*(j>>2) + 2*(j&3) + (g&1) + 8*(g>>1)
__device__ __forceinline__ int remap_row(int r) {
    const int g = r >> 9, j = r & 511;
    return ((j >> 2) << 4) + ((j & 3) << 1) + (g & 1) + ((g >> 1) << 3);
}

__global__ void prep_kernel(
    const float* __restrict__ x,
    const float* __restrict__ e0Wih, const float* __restrict__ e0Whh,
    const float* __restrict__ e0bih, const float* __restrict__ e0bhh,
    const float* __restrict__ e1Wih, const float* __restrict__ e1Whh,
    const float* __restrict__ e1bih, const float* __restrict__ e1bhh,
    const float* __restrict__ d0Wih, const float* __restrict__ d0Whh,
    const float* __restrict__ d0bih, const float* __restrict__ d0bhh,
    const float* __restrict__ d1Wih, const float* __restrict__ d1Whh,
    const float* __restrict__ d1bih, const float* __restrict__ d1bhh,
    const float* __restrict__ projb) {
    const size_t FULL = (size_t)N4 * Hd;
    long long idx = (long long)blockIdx.x * 256 + threadIdx.x;

    if (idx < (long long)(6 * FULL)) {
        int seg = (int)(idx / FULL);
        size_t i = (size_t)(idx % FULL);
        int r = (int)(i / Hd), k = (int)(i % Hd);
        size_t dst = (size_t)remap_row(r) * Hd + k;
        const float* src; f16* d;
        switch (seg) {
            case 0: src = e0Whh; d = gB_h0;  break;
            case 1: src = e1Wih; d = gB_x1;  break;
            case 2: src = e1Whh; d = gB_h1;  break;
            case 3: src = d0Whh; d = gB_d0;  break;
            case 4: src = d1Wih; d = gB_x1d; break;
            default: src = d1Whh; d = gB_d1; break;
        }
        d[dst] = __float2half(src[i]);
        return;
    }
    idx -= 6LL * FULL;

    if (idx < (long long)N4 * Fin) {   // Wx0
        size_t i = (size_t)idx;
        int r = (int)(i / Fin), k = (int)(i % Fin);
        gB_x0[(size_t)remap_row(r) * Fin + k] = __float2half(e0Wih[i]);
        return;
    }
    idx -= (long long)N4 * Fin;

    if (idx < (long long)Bsz * T_IN * Fin) {   // x -> [t][b][f]
        size_t i = (size_t)idx;
        int b = (int)(i / (T_IN * Fin));
        int t = (int)((i / Fin) % T_IN);
        int f = (int)(i % Fin);
        g_xc[(size_t)t * Bsz * Fin + b * Fin + f] = __float2half(x[i]);
        return;
    }
    idx -= (long long)Bsz * T_IN * Fin;

    if (idx < N4) {                    // biases + Wv, remapped (fp32)
        int r = (int)idx;
        int dst = remap_row(r);
        g_Wv[dst]  = d0Wih[r];
        g_b0[dst]  = e0bih[r] + e0bhh[r];
        g_b1[dst]  = e1bih[r] + e1bhh[r];
        g_bd0[dst] = d0bih[r] + d0bhh[r];
        g_bd1[dst] = d1bih[r] + d1bhh[r];
        return;
    }
    idx -= N4;

    if (idx < Bsz) {                   // prev slot0 = x[:, -1, -1]; slot1 = projb
        g_pacc[0][idx] = x[(size_t)(idx + 1) * T_IN * Fin - 1];
        g_pacc[1][idx] = projb[0];
        return;
    }
    idx -= Bsz;
    if (idx == 0) g_cnt = 0;
}

// ------------------------------ main kernel --------------------------------
__global__ void __launch_bounds__(THR, 1)
main_kernel(const float* __restrict__ projW,
            const float* __restrict__ projb,
            float* __restrict__ out) {
    extern __shared__ char dsm_raw[];
    const uint32_t raw32 = smem_u32(dsm_raw);
    const uint32_t dsm32 = (raw32 + 1023u) & ~1023u;

    const int tid  = threadIdx.x;
    const int lane = tid & 31;
    const int w    = tid >> 5;         // 0..7
    const int wm   = w & 1;            // M slice (32 rows)
    const int wn   = w >> 1;           // N slice (16 cols), 0..3
    const int bid  = blockIdx.x;       // 128 CTAs: 4M x 32N
    const int mT   = bid >> 5;
    const int nT   = bid & 31;
    const int bm   = mT * 64;
    const int colb = nT * 64;
    const int G16  = nT * 4 + wn;      // 16-col block = 4 units x 4 gates

    // Precompute swizzled LDSM offsets (stage-relative); hot loop is IADD-only.
    uint32_t asw[4], bsw[4];
    {
        const int abase = (wm * 32 + (lane & 15)) * 128 + ((lane >> 4) << 4);
        const int bbase = (wn * 16 + (lane & 7) + ((lane >> 4) << 3)) * 128
                        + (((lane >> 3) & 1) << 4);
#pragma unroll
        for (int ka = 0; ka < 4; ++ka) {
            const int ao = abase + ka * 32;
            asw[ka] = ao ^ ((ao >> 3) & 0x70);
            const int bo = bbase + ka * 32;
            bsw[ka] = OFF_B + (bo ^ ((bo >> 3) & 0x70));
        }
    }

    float accA[4][4], accB[4][4];
    float c0[4], c1[4];
#pragma unroll
    for (int i = 0; i < 4; ++i) { c0[i] = 0.0f; c1[i] = 0.0f; }

    Seg segs[4];

    // -------- fused encoder wavefront: superstep s = enc0(s) + enc1(s-1) ----
    for (int s = 0; s <= T_IN; ++s) {
        int ns = 0, split = 0;
        if (s < T_IN) {
            segs[ns++] = { g_xc + (size_t)s * Bsz * Fin, gB_x0, Fin };
            if (s) segs[ns++] = { g_hs + (size_t)(s - 1) * BH, gB_h0, Hd };
            split = s ? 9 : 1;
        }
        if (s >= 1) {
            segs[ns++] = { g_hs + (size_t)(s - 1) * BH, gB_x1, Hd };
            if (s >= 2) segs[ns++] = { &g_h1[s & 1][0], gB_h1, Hd };
        }
        ZERO_ACC(accA); ZERO_ACC(accB);
        pipe_gemm(dsm32, segs, ns, split, accA, accB, bm, colb, tid, asw, bsw);
        if (s < T_IN)
            epilogue_lstm(accA, c0, g_b0, nullptr, nullptr,
                          g_hs + (size_t)s * BH, nullptr, nullptr, bm, G16, wm, lane);
        if (s >= 1)
            epilogue_lstm(accB, c1, g_b1, nullptr, nullptr,
                          &g_h1[(s - 1) & 1][0], nullptr, nullptr, bm, G16, wm, lane);
        grid_sync();
    }

    // -------------------------------- decoder -------------------------------
    const f16 *h0p = g_hs + (size_t)(T_IN - 1) * BH;
    const f16 *h1p = &g_h1[(T_IN - 1) & 1][0];
    const float pjb = projb[0];

    for (int t = 0; t < T_OUT; ++t) {
        // phase A: dec0(t); side tasks: emit out[:,t-1], reseed next slot
        if (bid == 0 && t >= 1)
            out[(size_t)tid * T_OUT + (t - 1)] = g_pacc[t & 1][tid];
        if (bid == 1)
            g_pacc[(t + 1) & 1][tid] = pjb;

        segs[0] = { h0p, gB_d0, Hd };
        ZERO_ACC(accA);
        pipe_gemm(dsm32, segs, 1, 8, accA, accA, bm, colb, tid, asw, bsw);
        epilogue_lstm(accA, c0, g_bd0, &g_pacc[t & 1][0], g_Wv,
                      &g_d0[t & 1][0], nullptr, nullptr, bm, G16, wm, lane);
        grid_sync();

        // phase B: dec1(t) + fused projection into pacc[(t+1)&1]
        segs[0] = { &g_d0[t & 1][0], gB_x1d, Hd };
        segs[1] = { h1p, gB_d1, Hd };
        ZERO_ACC(accA);
        pipe_gemm(dsm32, segs, 2, 16, accA, accA, bm, colb, tid, asw, bsw);
        epilogue_lstm(accA, c1, g_bd1, nullptr, nullptr,
                      &g_d1[t & 1][0], projW, &g_pacc[(t + 1) & 1][0],
                      bm, G16, wm, lane);
        grid_sync();

        h0p = &g_d0[t & 1][0];
        h1p = &g_d1[t & 1][0];
    }

    // final output column (t = 63): slot (63+1)&1 = 0
    if (bid == 0)
        out[(size_t)tid * T_OUT + (T_OUT - 1)] = g_pacc[0][tid];
}

// ------------------------------- host side ---------------------------------
extern "C" void kernel_launch(void* const* d_in, const int* in_sizes, int n_in,
                              void* d_out, int out_size) {
    const float* x      = (const float*)d_in[0];
    const float* e0Wih  = (const float*)d_in[2];
    const float* e0Whh  = (const float*)d_in[3];
    const float* e0bih  = (const float*)d_in[4];
    const float* e0bhh  = (const float*)d_in[5];
    const float* e1Wih  = (const float*)d_in[6];
    const float* e1Whh  = (const float*)d_in[7];
    const float* e1bih  = (const float*)d_in[8];
    const float* e1bhh  = (const float*)d_in[9];
    const float* d0Wih  = (const float*)d_in[10];
    const float* d0Whh  = (const float*)d_in[11];
    const float* d0bih  = (const float*)d_in[12];
    const float* d0bhh  = (const float*)d_in[13];
    const float* d1Wih  = (const float*)d_in[14];
    const float* d1Whh  = (const float*)d_in[15];
    const float* d1bih  = (const float*)d_in[16];
    const float* d1bhh  = (const float*)d_in[17];
    const float* projW  = (const float*)d_in[18];
    const float* projb  = (const float*)d_in[19];
    float* out = (float*)d_out;

    const long long total = 6LL * N4 * Hd + (long long)N4 * Fin
                          + (long long)Bsz * T_IN * Fin + N4 + Bsz + 1;
    const int nblk = (int)((total + 255) / 256);
    prep_kernel<<<nblk, 256>>>(x,
        e0Wih, e0Whh, e0bih, e0bhh,
        e1Wih, e1Whh, e1bih, e1bhh,
        d0Wih, d0Whh, d0bih, d0bhh,
        d1Wih, d1Whh, d1bih, d1bhh, projb);

    cudaFuncSetAttribute(main_kernel, cudaFuncAttributeMaxDynamicSharedMemorySize, DSMEM);
    main_kernel<<<NBLK, THR, DSMEM>>>(projW, projb, out);
}

// round 15
// speedup vs baseline: 1.0137x; 1.0137x over previous
#include <cuda_runtime.h>
#include <cuda_fp16.h>
#include <cstdint>
#include <math.h>

// ---------------------------------------------------------------------------
// Seq2Seq LSTM via mma.sync (HMMA fp16): B=256, T_in=512, F=64, H=512, T_out=64
// Round 15: WEIGHT-RESIDENT SMEM. Each CTA loads its B (weight) slices into a
// 200KB resident smem region once per phase (encoder: Wx0|Wh0|Wx1|Wh1,
// decoder: Wd0|Wx1d|Wd1), ordered so chunk c's B tile sits at resbase+c*8192.
// The cp.async ring then streams ONLY A (3 stages x 8KB, 1 CP16/thread/chunk).
// Shape = round-13 champion: 128 CTAs, 512 thr, 16 warps of 16x16 tiles,
// fast-math epilogue, fused projection, encoder wavefront fusion.
// ---------------------------------------------------------------------------

using f16 = __half;

#define Bsz   256
#define Hd    512
#define Fin   64
#define T_IN  512
#define T_OUT 64
#define N4    2048
#define BH    (Bsz*Hd)
#define NBLK  128
#define THR   512

#define CHUNKB 8192                 // one 64x64 fp16 tile
#define RES_BYTES (25*CHUNKB)       // encoder: 1+8+8+8 chunks = 200KB
#define NSTAGE 3
#define DSMEM  (RES_BYTES + NSTAGE*CHUNKB + 1024)   // 230400 B

// ------------------------- device scratch (static) -------------------------
__device__ __align__(16) f16 g_xc[(size_t)T_IN * Bsz * Fin];
__device__ __align__(16) f16 g_hs[(size_t)T_IN * BH];
__device__ __align__(16) f16 g_h1[2][BH];
__device__ __align__(16) f16 g_d0[2][BH];
__device__ __align__(16) f16 g_d1[2][BH];
__device__ float g_pacc[2][Bsz];          // proj ping-pong accumulators

// weights, remapped rows (see remap_row), layout [2048][K] fp16
__device__ __align__(16) f16 gB_x0[N4 * Fin];
__device__ __align__(16) f16 gB_h0[N4 * Hd];
__device__ __align__(16) f16 gB_x1[N4 * Hd];
__device__ __align__(16) f16 gB_h1[N4 * Hd];
__device__ __align__(16) f16 gB_d0[N4 * Hd];
__device__ __align__(16) f16 gB_x1d[N4 * Hd];
__device__ __align__(16) f16 gB_d1[N4 * Hd];

__device__ __align__(16) float g_b0[N4], g_b1[N4], g_bd0[N4], g_bd1[N4], g_Wv[N4];

__device__ unsigned g_cnt;
__device__ volatile unsigned g_gen;

// ------------------------------- asm helpers -------------------------------
#define LDSM4(R, A) \
    asm volatile("ldmatrix.sync.aligned.m8n8.x4.shared.b16 {%0,%1,%2,%3}, [%4];" \
        : "=r"((R)[0]), "=r"((R)[1]), "=r"((R)[2]), "=r"((R)[3]) : "r"(A))

#define MMA(D, A, B) \
    asm volatile("mma.sync.aligned.m16n8k16.row.col.f32.f16.f16.f32 " \
        "{%0,%1,%2,%3}, {%4,%5,%6,%7}, {%8,%9}, {%0,%1,%2,%3};" \
        : "+f"((D)[0]), "+f"((D)[1]), "+f"((D)[2]), "+f"((D)[3]) \
        : "r"((A)[0]), "r"((A)[1]), "r"((A)[2]), "r"((A)[3]), \
          "r"((B)[0]), "r"((B)[1]))

#define CP16(sa, ga) \
    asm volatile("cp.async.cg.shared.global [%0], [%1], 16;" :: "r"(sa), "l"(ga))
#define CP_COMMIT() asm volatile("cp.async.commit_group;")
#define CP_WAIT0()  asm volatile("cp.async.wait_group 0;" ::: "memory")
#define CP_WAIT1()  asm volatile("cp.async.wait_group 1;" ::: "memory")

__device__ __forceinline__ uint32_t smem_u32(const void* p) {
    uint32_t a;
    asm("{ .reg .u64 t; cvta.to.shared.u64 t, %1; cvt.u32.u64 %0, t; }"
        : "=r"(a) : "l"(p));
    return a;
}

// Fast activations: MUFU-based. |err| ~2^-21, far below fp16 gate noise.
__device__ __forceinline__ float sigf(float x) {
    return __fdividef(1.0f, 1.0f + __expf(-x));
}
__device__ __forceinline__ float tanhf_fast(float x) {
    return 1.0f - __fdividef(2.0f, __expf(2.0f * x) + 1.0f);
}

__device__ __forceinline__ void grid_sync() {
    __syncthreads();
    if (threadIdx.x == 0) {
        __threadfence();
        unsigned g = g_gen;
        unsigned old = atomicAdd(&g_cnt, 1u);
        if (old == NBLK - 1) {
            g_cnt = 0;
            __threadfence();
            g_gen = g + 1;
        } else {
            while (g_gen == g) __nanosleep(64);
            __threadfence();
        }
    }
    __syncthreads();
}

// ----------------------------- GEMM machinery ------------------------------
struct SegA {
    const f16 *A;   // A [row][K]
    int K;          // 64 or 512
};

// Warp tile 16x16, fp16; LDSM offsets precomputed. A from ring, B resident.
__device__ __forceinline__ void compute_chunk(uint32_t abase, uint32_t bbase,
                                              float acc[2][4],
                                              const uint32_t* asw,
                                              const uint32_t* bsw) {
#pragma unroll
    for (int ka = 0; ka < 4; ++ka) {
        uint32_t a[4], b[4];
        LDSM4(a, abase + asw[ka]);
        LDSM4(b, bbase + bsw[ka]);
        MMA(acc[0], a, b);
        MMA(acc[1], a, b + 2);
    }
}

// A-only 3-stage ring (8KB stages); B tiles resident at bres + c*8192.
__device__ __forceinline__ void pipe_gemm(uint32_t ringb, uint32_t bres,
                                          const SegA* segs, int nseg, int split,
                                          float aA[2][4], float aB[2][4],
                                          int bm, int tid,
                                          const uint32_t* asw, const uint32_t* bsw) {
    int tot = 0;
#pragma unroll
    for (int i = 0; i < 4; ++i) if (i < nseg) tot += segs[i].K >> 6;

    const int row = tid >> 3, sg8 = (tid & 7) * 8;
    const uint32_t swA = (uint32_t)((tid * 16) ^ (((tid * 16) >> 3) & 0x70));
    const int ra512 = (bm + row) * 512 + sg8;

    const f16* pA = segs[0].A + (segs[0].K == 64 ? (bm + row) * 64 + sg8 : ra512);
    int rem = segs[0].K >> 6;
    int si = 0;
    uint32_t ibase = ringb;
    const uint32_t wrap = ringb + NSTAGE * CHUNKB;

    auto issue1 = [&]() {
        CP16(ibase + swA, pA);
        ibase += CHUNKB;
        if (ibase == wrap) ibase = ringb;
        if (--rem == 0) {
            ++si;
            if (si == 1 && nseg > 1) { pA = segs[1].A + ra512; rem = segs[1].K >> 6; }
            else if (si == 2 && nseg > 2) { pA = segs[2].A + ra512; rem = segs[2].K >> 6; }
            else if (si == 3 && nseg > 3) { pA = segs[3].A + ra512; rem = segs[3].K >> 6; }
        } else {
            pA += 64;
        }
    };

    // prefill 2 chunks
    issue1();
    CP_COMMIT();
    if (tot > 1) { issue1(); CP_COMMIT(); }

    uint32_t cbase = ringb;
    uint32_t bbase = bres;
    for (int c = 0; c < tot; ++c) {
        if (c + 1 < tot) CP_WAIT1();
        else             CP_WAIT0();
        __syncthreads();
        if (c + 2 < tot) { issue1(); CP_COMMIT(); }
        compute_chunk(cbase, bbase, c < split ? aA : aB, asw, bsw);
        cbase += CHUNKB;
        if (cbase == wrap) cbase = ringb;
        bbase += CHUNKB;
    }
}

#define ZERO_ACC(A) \
    do { _Pragma("unroll") for (int _a = 0; _a < 2; ++_a) \
         _Pragma("unroll") for (int _d = 0; _d < 4; ++_d) (A)[_a][_d] = 0.0f; } while (0)

// Epilogue: thread owns rows {m, m+8} x ONE unit (all 4 gates).
__device__ __forceinline__ void epilogue_lstm(float acc[2][4], float* c,
                                              const float* bias,
                                              const float* prevv, const float* Wv,
                                              f16* H,
                                              const float* pjW, float* pacc,
                                              int bm, int G16, int wm, int lane) {
    const int q = lane & 3, r = lane >> 2;
    const float2* b2 = (const float2*)bias;
    const float2 bIF = __ldg(&b2[G16 * 8 + q]);
    const float2 bGO = __ldg(&b2[G16 * 8 + 4 + q]);
    float2 wIF = make_float2(0.f, 0.f), wGO = make_float2(0.f, 0.f);
    if (Wv) {
        const float2* w2 = (const float2*)Wv;
        wIF = __ldg(&w2[G16 * 8 + q]);
        wGO = __ldg(&w2[G16 * 8 + 4 + q]);
    }
    const int u = G16 * 4 + q;
    float pw = 0.0f;
    if (pjW) pw = __ldg(&pjW[u]);
    float rsum[2] = {0.0f, 0.0f};
#pragma unroll
    for (int rr = 0; rr < 2; ++rr) {
        const int m = bm + wm * 16 + r + rr * 8;
        float gi = acc[0][rr * 2 + 0] + bIF.x;
        float gf = acc[0][rr * 2 + 1] + bIF.y;
        float gg = acc[1][rr * 2 + 0] + bGO.x;
        float go = acc[1][rr * 2 + 1] + bGO.y;
        if (prevv) {
            const float pv = prevv[m];
            gi = fmaf(pv, wIF.x, gi); gf = fmaf(pv, wIF.y, gf);
            gg = fmaf(pv, wGO.x, gg); go = fmaf(pv, wGO.y, go);
        }
        float cn = sigf(gf) * c[rr] + sigf(gi) * tanhf_fast(gg);
        float hn = sigf(go) * tanhf_fast(cn);
        c[rr] = cn;
        if (pjW) rsum[rr] = hn * pw;
        H[(size_t)m * Hd + u] = __float2half(hn);
    }
    if (pjW) {
#pragma unroll
        for (int rr = 0; rr < 2; ++rr) {
            rsum[rr] += __shfl_xor_sync(0xffffffffu, rsum[rr], 1);
            rsum[rr] += __shfl_xor_sync(0xffffffffu, rsum[rr], 2);
        }
        if (q == 0) {
            atomicAdd(&pacc[bm + wm * 16 + r], rsum[0]);
            atomicAdd(&pacc[bm + wm * 16 + r + 8], rsum[1]);
        }
    }
}

// ------------------------------- prep kernel -------------------------------
// gate g (0..3), unit j (0..511) -> col = 16*(j>>2) + 2*(j&3) + (g&1) + 8*(g>>1)
__device__ __forceinline__ int remap_row(int r) {
    const int g = r >> 9, j = r & 511;
    return ((j >> 2) << 4) + ((j & 3) << 1) + (g & 1) + ((g >> 1) << 3);
}

__global__ void prep_kernel(
    const float* __restrict__ x,
    const float* __restrict__ e0Wih, const float* __restrict__ e0Whh,
    const float* __restrict__ e0bih, const float* __restrict__ e0bhh,
    const float* __restrict__ e1Wih, const float* __restrict__ e1Whh,
    const float* __restrict__ e1bih, const float* __restrict__ e1bhh,
    const float* __restrict__ d0Wih, const float* __restrict__ d0Whh,
    const float* __restrict__ d0bih, const float* __restrict__ d0bhh,
    const float* __restrict__ d1Wih, const float* __restrict__ d1Whh,
    const float* __restrict__ d1bih, const float* __restrict__ d1bhh,
    const float* __restrict__ projb) {
    const size_t FULL = (size_t)N4 * Hd;
    long long idx = (long long)blockIdx.x * 256 + threadIdx.x;

    if (idx < (long long)(6 * FULL)) {
        int seg = (int)(idx / FULL);
        size_t i = (size_t)(idx % FULL);
        int r = (int)(i / Hd), k = (int)(i % Hd);
        size_t dst = (size_t)remap_row(r) * Hd + k;
        const float* src; f16* d;
        switch (seg) {
            case 0: src = e0Whh; d = gB_h0;  break;
            case 1: src = e1Wih; d = gB_x1;  break;
            case 2: src = e1Whh; d = gB_h1;  break;
            case 3: src = d0Whh; d = gB_d0;  break;
            case 4: src = d1Wih; d = gB_x1d; break;
            default: src = d1Whh; d = gB_d1; break;
        }
        d[dst] = __float2half(src[i]);
        return;
    }
    idx -= 6LL * FULL;

    if (idx < (long long)N4 * Fin) {   // Wx0
        size_t i = (size_t)idx;
        int r = (int)(i / Fin), k = (int)(i % Fin);
        gB_x0[(size_t)remap_row(r) * Fin + k] = __float2half(e0Wih[i]);
        return;
    }
    idx -= (long long)N4 * Fin;

    if (idx < (long long)Bsz * T_IN * Fin) {   // x -> [t][b][f]
        size_t i = (size_t)idx;
        int b = (int)(i / (T_IN * Fin));
        int t = (int)((i / Fin) % T_IN);
        int f = (int)(i % Fin);
        g_xc[(size_t)t * Bsz * Fin + b * Fin + f] = __float2half(x[i]);
        return;
    }
    idx -= (long long)Bsz * T_IN * Fin;

    if (idx < N4) {                    // biases + Wv, remapped (fp32)
        int r = (int)idx;
        int dst = remap_row(r);
        g_Wv[dst]  = d0Wih[r];
        g_b0[dst]  = e0bih[r] + e0bhh[r];
        g_b1[dst]  = e1bih[r] + e1bhh[r];
        g_bd0[dst] = d0bih[r] + d0bhh[r];
        g_bd1[dst] = d1bih[r] + d1bhh[r];
        return;
    }
    idx -= N4;

    if (idx < Bsz) {                   // prev slot0 = x[:, -1, -1]; slot1 = projb
        g_pacc[0][idx] = x[(size_t)(idx + 1) * T_IN * Fin - 1];
        g_pacc[1][idx] = projb[0];
        return;
    }
    idx -= Bsz;
    if (idx == 0) g_cnt = 0;
}

// ------------------------------ main kernel --------------------------------
__global__ void __launch_bounds__(THR, 1)
main_kernel(const float* __restrict__ projW,
            const float* __restrict__ projb,
            float* __restrict__ out) {
    extern __shared__ char dsm_raw[];
    const uint32_t raw32 = smem_u32(dsm_raw);
    const uint32_t resb  = (raw32 + 1023u) & ~1023u;   // resident B region
    const uint32_t ringb = resb + RES_BYTES;           // A ring

    const int tid  = threadIdx.x;
    const int lane = tid & 31;
    const int w    = tid >> 5;         // 0..15
    const int wm   = w & 3;            // M slice (16 rows)
    const int wn   = w >> 2;           // N slice (16 cols)
    const int bid  = blockIdx.x;       // 128 CTAs: 4M x 32N
    const int mT   = bid >> 5;
    const int nT   = bid & 31;
    const int bm   = mT * 64;
    const int colb = nT * 64;
    const int G16  = nT * 4 + wn;      // 16-col block = 4 units x 4 gates

    // Precomputed swizzled LDSM offsets (tile-relative).
    uint32_t asw[4], bsw[4];
    {
        const int abase = (wm * 16 + (lane & 15)) * 128 + ((lane >> 4) << 4);
        const int bbase = (wn * 16 + (lane & 7) + ((lane >> 4) << 3)) * 128
                        + (((lane >> 3) & 1) << 4);
#pragma unroll
        for (int ka = 0; ka < 4; ++ka) {
            const int ao = abase + ka * 32;
            asw[ka] = ao ^ ((ao >> 3) & 0x70);
            const int bo = bbase + ka * 32;
            bsw[ka] = bo ^ ((bo >> 3) & 0x70);
        }
    }

    const int rrow = tid >> 3, rsg8 = (tid & 7) * 8;
    const uint32_t rsw = (uint32_t)((tid * 16) ^ (((tid * 16) >> 3) & 0x70));

    // ---- one-time encoder resident B load: [Wx0 | Wh0 | Wx1 | Wh1] ----
    {
        uint32_t dst = resb + rsw;
        CP16(dst, gB_x0 + (colb + rrow) * 64 + rsg8);
        dst += CHUNKB;
        const f16* mats[3] = { gB_h0, gB_x1, gB_h1 };
#pragma unroll
        for (int mi = 0; mi < 3; ++mi) {
            const f16* p = mats[mi] + (colb + rrow) * 512 + rsg8;
#pragma unroll
            for (int ck = 0; ck < 8; ++ck) {
                CP16(dst, p);
                dst += CHUNKB;
                p += 64;
            }
        }
        CP_COMMIT();
        CP_WAIT0();
        __syncthreads();
    }

    float accA[2][4], accB[2][4];
    float c0[2], c1[2];
    c0[0] = c0[1] = c1[0] = c1[1] = 0.0f;

    SegA segs[4];

    // -------- fused encoder wavefront: superstep s = enc0(s) + enc1(s-1) ----
    // Resident B chunk order == consumption order: x0(1), h0(8), x1(8), h1(8).
    for (int s = 0; s <= T_IN; ++s) {
        int ns = 0, split = 0;
        uint32_t bres = resb;
        if (s < T_IN) {
            segs[ns++] = { g_xc + (size_t)s * Bsz * Fin, Fin };
            if (s) segs[ns++] = { g_hs + (size_t)(s - 1) * BH, Hd };
            split = s ? 9 : 1;
        } else {
            bres = resb + 9 * CHUNKB;    // final superstep: only x1[,h1]
        }
        if (s >= 1) {
            segs[ns++] = { g_hs + (size_t)(s - 1) * BH, Hd };
            if (s >= 2) segs[ns++] = { &g_h1[s & 1][0], Hd };
        }
        ZERO_ACC(accA); ZERO_ACC(accB);
        pipe_gemm(ringb, bres, segs, ns, split, accA, accB, bm, tid, asw, bsw);
        if (s < T_IN)
            epilogue_lstm(accA, c0, g_b0, nullptr, nullptr,
                          g_hs + (size_t)s * BH, nullptr, nullptr, bm, G16, wm, lane);
        if (s >= 1)
            epilogue_lstm(accB, c1, g_b1, nullptr, nullptr,
                          &g_h1[(s - 1) & 1][0], nullptr, nullptr, bm, G16, wm, lane);
        grid_sync();
    }

    // ---- one-time decoder resident B load: [Wd0 | Wx1d | Wd1] ----
    {
        uint32_t dst = resb + rsw;
        const f16* mats[3] = { gB_d0, gB_x1d, gB_d1 };
#pragma unroll
        for (int mi = 0; mi < 3; ++mi) {
            const f16* p = mats[mi] + (colb + rrow) * 512 + rsg8;
#pragma unroll
            for (int ck = 0; ck < 8; ++ck) {
                CP16(dst, p);
                dst += CHUNKB;
                p += 64;
            }
        }
        CP_COMMIT();
        CP_WAIT0();
        __syncthreads();
    }

    // -------------------------------- decoder -------------------------------
    const f16 *h0p = g_hs + (size_t)(T_IN - 1) * BH;
    const f16 *h1p = &g_h1[(T_IN - 1) & 1][0];
    const float pjb = projb[0];

    for (int t = 0; t < T_OUT; ++t) {
        // phase A: dec0(t); side tasks: emit out[:,t-1], reseed next slot
        if (bid == 0 && tid < Bsz && t >= 1)
            out[(size_t)tid * T_OUT + (t - 1)] = g_pacc[t & 1][tid];
        if (bid == 1 && tid < Bsz)
            g_pacc[(t + 1) & 1][tid] = pjb;

        segs[0] = { h0p, Hd };
        ZERO_ACC(accA);
        pipe_gemm(ringb, resb, segs, 1, 8, accA, accA, bm, tid, asw, bsw);
        epilogue_lstm(accA, c0, g_bd0, &g_pacc[t & 1][0], g_Wv,
                      &g_d0[t & 1][0], nullptr, nullptr, bm, G16, wm, lane);
        grid_sync();

        // phase B: dec1(t) + fused projection into pacc[(t+1)&1]
        segs[0] = { &g_d0[t & 1][0], Hd };
        segs[1] = { h1p, Hd };
        ZERO_ACC(accA);
        pipe_gemm(ringb, resb + 8 * CHUNKB, segs, 2, 16, accA, accA, bm, tid, asw, bsw);
        epilogue_lstm(accA, c1, g_bd1, nullptr, nullptr,
                      &g_d1[t & 1][0], projW, &g_pacc[(t + 1) & 1][0],
                      bm, G16, wm, lane);
        grid_sync();

        h0p = &g_d0[t & 1][0];
        h1p = &g_d1[t & 1][0];
    }

    // final output column (t = 63): slot (63+1)&1 = 0
    if (bid == 0 && tid < Bsz)
        out[(size_t)tid * T_OUT + (T_OUT - 1)] = g_pacc[0][tid];
}

// ------------------------------- host side ---------------------------------
extern "C" void kernel_launch(void* const* d_in, const int* in_sizes, int n_in,
                              void* d_out, int out_size) {
    const float* x      = (const float*)d_in[0];
    const float* e0Wih  = (const float*)d_in[2];
    const float* e0Whh  = (const float*)d_in[3];
    const float* e0bih  = (const float*)d_in[4];
    const float* e0bhh  = (const float*)d_in[5];
    const float* e1Wih  = (const float*)d_in[6];
    const float* e1Whh  = (const float*)d_in[7];
    const float* e1bih  = (const float*)d_in[8];
    const float* e1bhh  = (const float*)d_in[9];
    const float* d0Wih  = (const float*)d_in[10];
    const float* d0Whh  = (const float*)d_in[11];
    const float* d0bih  = (const float*)d_in[12];
    const float* d0bhh  = (const float*)d_in[13];
    const float* d1Wih  = (const float*)d_in[14];
    const float* d1Whh  = (const float*)d_in[15];
    const float* d1bih  = (const float*)d_in[16];
    const float* d1bhh  = (const float*)d_in[17];
    const float* projW  = (const float*)d_in[18];
    const float* projb  = (const float*)d_in[19];
    float* out = (float*)d_out;

    const long long total = 6LL * N4 * Hd + (long long)N4 * Fin
                          + (long long)Bsz * T_IN * Fin + N4 + Bsz + 1;
    const int nblk = (int)((total + 255) / 256);
    prep_kernel<<<nblk, 256>>>(x,
        e0Wih, e0Whh, e0bih, e0bhh,
        e1Wih, e1Whh, e1bih, e1bhh,
        d0Wih, d0Whh, d0bih, d0bhh,
        d1Wih, d1Whh, d1bih, d1bhh, projb);

    cudaFuncSetAttribute(main_kernel, cudaFuncAttributeMaxDynamicSharedMemorySize, DSMEM);
    main_kernel<<<NBLK, THR, DSMEM>>>(projW, projb, out);
}

// round 16
// speedup vs baseline: 1.1010x; 1.0861x over previous
#include <cuda_runtime.h>
#include <cuda_fp16.h>
#include <cstdint>
#include <math.h>

// ---------------------------------------------------------------------------
// Seq2Seq LSTM via mma.sync (HMMA fp16): B=256, T_in=512, F=64, H=512, T_out=64
// Round 16: R13 champion + SPLIT-PHASE grid barrier. After each superstep's
// epilogue: arrive -> issue+compute the barrier-independent x0 chunk -> wait
// -> run remaining chunks (quad pipeline unchanged). Hides barrier release
// latency behind ~1 chunk of compute. Tighter spin (nanosleep 32).
// 128 CTAs, 512 thr, 16 warps of 16x16 tiles, 12-stage quad ring, fast-math
// epilogue, fused projection, encoder wavefront fusion.
// ---------------------------------------------------------------------------

using f16 = __half;

#define Bsz   256
#define Hd    512
#define Fin   64
#define T_IN  512
#define T_OUT 64
#define N4    2048
#define BH    (Bsz*Hd)
#define NBLK  128
#define THR   512

// per-stage smem: A 8K | B 8K
#define OFF_B  8192
#define BUFB   16384
#define NSTAGE 12
#define DSMEM  (NSTAGE*BUFB + 1024)

// ------------------------- device scratch (static) -------------------------
__device__ __align__(16) f16 g_xc[(size_t)T_IN * Bsz * Fin];
__device__ __align__(16) f16 g_hs[(size_t)T_IN * BH];
__device__ __align__(16) f16 g_h1[2][BH];
__device__ __align__(16) f16 g_d0[2][BH];
__device__ __align__(16) f16 g_d1[2][BH];
__device__ float g_pacc[2][Bsz];          // proj ping-pong accumulators

// weights, remapped rows (see remap_row), layout [2048][K] fp16
__device__ __align__(16) f16 gB_x0[N4 * Fin];
__device__ __align__(16) f16 gB_h0[N4 * Hd];
__device__ __align__(16) f16 gB_x1[N4 * Hd];
__device__ __align__(16) f16 gB_h1[N4 * Hd];
__device__ __align__(16) f16 gB_d0[N4 * Hd];
__device__ __align__(16) f16 gB_x1d[N4 * Hd];
__device__ __align__(16) f16 gB_d1[N4 * Hd];

__device__ __align__(16) float g_b0[N4], g_b1[N4], g_bd0[N4], g_bd1[N4], g_Wv[N4];

__device__ unsigned g_cnt;
__device__ volatile unsigned g_gen;

// ------------------------------- asm helpers -------------------------------
#define LDSM4(R, A) \
    asm volatile("ldmatrix.sync.aligned.m8n8.x4.shared.b16 {%0,%1,%2,%3}, [%4];" \
        : "=r"((R)[0]), "=r"((R)[1]), "=r"((R)[2]), "=r"((R)[3]) : "r"(A))

#define MMA(D, A, B) \
    asm volatile("mma.sync.aligned.m16n8k16.row.col.f32.f16.f16.f32 " \
        "{%0,%1,%2,%3}, {%4,%5,%6,%7}, {%8,%9}, {%0,%1,%2,%3};" \
        : "+f"((D)[0]), "+f"((D)[1]), "+f"((D)[2]), "+f"((D)[3]) \
        : "r"((A)[0]), "r"((A)[1]), "r"((A)[2]), "r"((A)[3]), \
          "r"((B)[0]), "r"((B)[1]))

#define CP16(sa, ga) \
    asm volatile("cp.async.cg.shared.global [%0], [%1], 16;" :: "r"(sa), "l"(ga))
#define CP_COMMIT() asm volatile("cp.async.commit_group;")
#define CP_WAIT0()  asm volatile("cp.async.wait_group 0;" ::: "memory")
#define CP_WAIT1()  asm volatile("cp.async.wait_group 1;" ::: "memory")

__device__ __forceinline__ uint32_t smem_u32(const void* p) {
    uint32_t a;
    asm("{ .reg .u64 t; cvta.to.shared.u64 t, %1; cvt.u32.u64 %0, t; }"
        : "=r"(a) : "l"(p));
    return a;
}

// Fast activations: MUFU-based. |err| ~2^-21, far below fp16 gate noise.
__device__ __forceinline__ float sigf(float x) {
    return __fdividef(1.0f, 1.0f + __expf(-x));
}
__device__ __forceinline__ float tanhf_fast(float x) {
    return 1.0f - __fdividef(2.0f, __expf(2.0f * x) + 1.0f);
}

// ---- split-phase grid barrier (sense = generation counter) ----
// Every CTA: arrive exactly once per generation; wait (on the gen captured at
// arrive) before the next arrive. Between arrive and wait a CTA may only
// touch static data / private smem.
__device__ __forceinline__ void arrive_gs(unsigned& mygen) {
    __syncthreads();                      // all epilogue stores + smem quiesced
    if (threadIdx.x == 0) {
        __threadfence();
        unsigned g = g_gen;
        mygen = g;
        unsigned old = atomicAdd(&g_cnt, 1u);
        if (old == NBLK - 1) {
            g_cnt = 0;
            __threadfence();
            g_gen = g + 1;
        }
    }
}
__device__ __forceinline__ void wait_gs(unsigned mygen) {
    if (threadIdx.x == 0) {
        while (g_gen == mygen) __nanosleep(32);
        __threadfence();
    }
    __syncthreads();
}

// ----------------------------- GEMM machinery ------------------------------
struct Seg {
    const f16 *A;   // A [row][K]
    const f16 *B;   // B' [2048][K]
    int K;          // 64 or 512
};

// Warp tile 16x16, single pass fp16; all LDSM offsets precomputed.
__device__ __forceinline__ void compute_chunk(uint32_t sbase, float acc[2][4],
                                              const uint32_t* asw,
                                              const uint32_t* bsw) {
#pragma unroll
    for (int ka = 0; ka < 4; ++ka) {
        uint32_t a[4], b[4];
        LDSM4(a, sbase + asw[ka]);
        LDSM4(b, sbase + bsw[ka]);
        MMA(acc[0], a, b);
        MMA(acc[1], a, b + 2);
    }
}

// Barrier-independent x0 chunk: A = x_t slice, B = Wx0 (both static).
// Uses ring stage 0; caller guarantees stage quiescence (arrive's sync).
__device__ __forceinline__ void chunk0_x0(uint32_t dsm32, const f16* Ax,
                                          float acc[2][4], int bm, int colb,
                                          int tid, const uint32_t* asw,
                                          const uint32_t* bsw) {
    const int row = tid >> 3, sg8 = (tid & 7) * 8;
    const uint32_t swA = (uint32_t)((tid * 16) ^ (((tid * 16) >> 3) & 0x70));
    CP16(dsm32 + swA, Ax + (bm + row) * 64 + sg8);
    CP16(dsm32 + OFF_B + swA, gB_x0 + (colb + row) * 64 + sg8);
    CP_COMMIT();
    CP_WAIT0();
    __syncthreads();
    compute_chunk(dsm32, acc, asw, bsw);
    __syncthreads();                 // stage 0 free for the pipeline prefill
}

// 12-stage ring, QUAD groups: one wait + one syncthreads per 4 chunks.
__device__ __forceinline__ void pipe_gemm(uint32_t dsm32, const Seg* segs, int nseg,
                                          int split, float aA[2][4], float aB[2][4],
                                          int bm, int colb, int tid,
                                          const uint32_t* asw, const uint32_t* bsw) {
    int tot = 0;
#pragma unroll
    for (int i = 0; i < 4; ++i) if (i < nseg) tot += segs[i].K >> 6;
    const int G = (tot + 3) >> 2;

    const int row = tid >> 3, sg8 = (tid & 7) * 8;
    const uint32_t swA = (uint32_t)((tid * 16) ^ (((tid * 16) >> 3) & 0x70));
    const uint32_t swB = swA + OFF_B;
    const int ra512 = (bm + row) * 512 + sg8;
    const int rb512 = (colb + row) * 512 + sg8;

    // issue cursor: walking pointers, reseed at (rare) segment boundaries
    const f16* pA = segs[0].A + (segs[0].K == 64 ? (bm + row) * 64 + sg8 : ra512);
    const f16* pB = segs[0].B + (segs[0].K == 64 ? (colb + row) * 64 + sg8 : rb512);
    int rem = segs[0].K >> 6;
    int si = 0;
    int issued = 0;
    uint32_t ibase = dsm32;
    const uint32_t wrap = dsm32 + NSTAGE * BUFB;

    auto issue1 = [&]() {
        CP16(ibase + swA, pA);
        CP16(ibase + swB, pB);
        ibase += BUFB;
        if (ibase == wrap) ibase = dsm32;
        ++issued;
        if (--rem == 0) {
            ++si;
            if (si == 1 && nseg > 1) { pA = segs[1].A + ra512; pB = segs[1].B + rb512; rem = segs[1].K >> 6; }
            else if (si == 2 && nseg > 2) { pA = segs[2].A + ra512; pB = segs[2].B + rb512; rem = segs[2].K >> 6; }
            else if (si == 3 && nseg > 3) { pA = segs[3].A + ra512; pB = segs[3].B + rb512; rem = segs[3].K >> 6; }
        } else {
            pA += 64;
            pB += 64;
        }
    };

    // prefill 2 groups
    {
        const int pre = G < 2 ? G : 2;
        for (int g = 0; g < pre; ++g) {
#pragma unroll
            for (int j = 0; j < 4; ++j) if (issued < tot) issue1();
            CP_COMMIT();
        }
    }

    uint32_t cbase = dsm32;
    int c = 0;
    for (int g = 0; g < G; ++g) {
        if (g + 1 < G) CP_WAIT1();
        else           CP_WAIT0();
        __syncthreads();
        if (g + 2 < G) {
#pragma unroll
            for (int j = 0; j < 4; ++j) if (issued < tot) issue1();
            CP_COMMIT();
        }
#pragma unroll
        for (int j = 0; j < 4; ++j) {
            if (c < tot) {
                compute_chunk(cbase, c < split ? aA : aB, asw, bsw);
                cbase += BUFB;
                if (cbase == wrap) cbase = dsm32;
                ++c;
            }
        }
    }
}

#define ZERO_ACC(A) \
    do { _Pragma("unroll") for (int _a = 0; _a < 2; ++_a) \
         _Pragma("unroll") for (int _d = 0; _d < 4; ++_d) (A)[_a][_d] = 0.0f; } while (0)

// Epilogue: thread owns rows {m, m+8} x ONE unit (all 4 gates).
__device__ __forceinline__ void epilogue_lstm(float acc[2][4], float* c,
                                              const float* bias,
                                              const float* prevv, const float* Wv,
                                              f16* H,
                                              const float* pjW, float* pacc,
                                              int bm, int G16, int wm, int lane) {
    const int q = lane & 3, r = lane >> 2;
    const float2* b2 = (const float2*)bias;
    const float2 bIF = __ldg(&b2[G16 * 8 + q]);
    const float2 bGO = __ldg(&b2[G16 * 8 + 4 + q]);
    float2 wIF = make_float2(0.f, 0.f), wGO = make_float2(0.f, 0.f);
    if (Wv) {
        const float2* w2 = (const float2*)Wv;
        wIF = __ldg(&w2[G16 * 8 + q]);
        wGO = __ldg(&w2[G16 * 8 + 4 + q]);
    }
    const int u = G16 * 4 + q;
    float pw = 0.0f;
    if (pjW) pw = __ldg(&pjW[u]);
    float rsum[2] = {0.0f, 0.0f};
#pragma unroll
    for (int rr = 0; rr < 2; ++rr) {
        const int m = bm + wm * 16 + r + rr * 8;
        float gi = acc[0][rr * 2 + 0] + bIF.x;
        float gf = acc[0][rr * 2 + 1] + bIF.y;
        float gg = acc[1][rr * 2 + 0] + bGO.x;
        float go = acc[1][rr * 2 + 1] + bGO.y;
        if (prevv) {
            const float pv = prevv[m];
            gi = fmaf(pv, wIF.x, gi); gf = fmaf(pv, wIF.y, gf);
            gg = fmaf(pv, wGO.x, gg); go = fmaf(pv, wGO.y, go);
        }
        float cn = sigf(gf) * c[rr] + sigf(gi) * tanhf_fast(gg);
        float hn = sigf(go) * tanhf_fast(cn);
        c[rr] = cn;
        if (pjW) rsum[rr] = hn * pw;
        H[(size_t)m * Hd + u] = __float2half(hn);
    }
    if (pjW) {
#pragma unroll
        for (int rr = 0; rr < 2; ++rr) {
            rsum[rr] += __shfl_xor_sync(0xffffffffu, rsum[rr], 1);
            rsum[rr] += __shfl_xor_sync(0xffffffffu, rsum[rr], 2);
        }
        if (q == 0) {
            atomicAdd(&pacc[bm + wm * 16 + r], rsum[0]);
            atomicAdd(&pacc[bm + wm * 16 + r + 8], rsum[1]);
        }
    }
}

// ------------------------------- prep kernel -------------------------------
// gate g (0..3), unit j (0..511) -> col = 16*(j>>2) + 2*(j&3) + (g&1) + 8*(g>>1)
__device__ __forceinline__ int remap_row(int r) {
    const int g = r >> 9, j = r & 511;
    return ((j >> 2) << 4) + ((j & 3) << 1) + (g & 1) + ((g >> 1) << 3);
}

__global__ void prep_kernel(
    const float* __restrict__ x,
    const float* __restrict__ e0Wih, const float* __restrict__ e0Whh,
    const float* __restrict__ e0bih, const float* __restrict__ e0bhh,
    const float* __restrict__ e1Wih, const float* __restrict__ e1Whh,
    const float* __restrict__ e1bih, const float* __restrict__ e1bhh,
    const float* __restrict__ d0Wih, const float* __restrict__ d0Whh,
    const float* __restrict__ d0bih, const float* __restrict__ d0bhh,
    const float* __restrict__ d1Wih, const float* __restrict__ d1Whh,
    const float* __restrict__ d1bih, const float* __restrict__ d1bhh,
    const float* __restrict__ projb) {
    const size_t FULL = (size_t)N4 * Hd;
    long long idx = (long long)blockIdx.x * 256 + threadIdx.x;

    if (idx < (long long)(6 * FULL)) {
        int seg = (int)(idx / FULL);
        size_t i = (size_t)(idx % FULL);
        int r = (int)(i / Hd), k = (int)(i % Hd);
        size_t dst = (size_t)remap_row(r) * Hd + k;
        const float* src; f16* d;
        switch (seg) {
            case 0: src = e0Whh; d = gB_h0;  break;
            case 1: src = e1Wih; d = gB_x1;  break;
            case 2: src = e1Whh; d = gB_h1;  break;
            case 3: src = d0Whh; d = gB_d0;  break;
            case 4: src = d1Wih; d = gB_x1d; break;
            default: src = d1Whh; d = gB_d1; break;
        }
        d[dst] = __float2half(src[i]);
        return;
    }
    idx -= 6LL * FULL;

    if (idx < (long long)N4 * Fin) {   // Wx0
        size_t i = (size_t)idx;
        int r = (int)(i / Fin), k = (int)(i % Fin);
        gB_x0[(size_t)remap_row(r) * Fin + k] = __float2half(e0Wih[i]);
        return;
    }
    idx -= (long long)N4 * Fin;

    if (idx < (long long)Bsz * T_IN * Fin) {   // x -> [t][b][f]
        size_t i = (size_t)idx;
        int b = (int)(i / (T_IN * Fin));
        int t = (int)((i / Fin) % T_IN);
        int f = (int)(i % Fin);
        g_xc[(size_t)t * Bsz * Fin + b * Fin + f] = __float2half(x[i]);
        return;
    }
    idx -= (long long)Bsz * T_IN * Fin;

    if (idx < N4) {                    // biases + Wv, remapped (fp32)
        int r = (int)idx;
        int dst = remap_row(r);
        g_Wv[dst]  = d0Wih[r];
        g_b0[dst]  = e0bih[r] + e0bhh[r];
        g_b1[dst]  = e1bih[r] + e1bhh[r];
        g_bd0[dst] = d0bih[r] + d0bhh[r];
        g_bd1[dst] = d1bih[r] + d1bhh[r];
        return;
    }
    idx -= N4;

    if (idx < Bsz) {                   // prev slot0 = x[:, -1, -1]; slot1 = projb
        g_pacc[0][idx] = x[(size_t)(idx + 1) * T_IN * Fin - 1];
        g_pacc[1][idx] = projb[0];
        return;
    }
    idx -= Bsz;
    if (idx == 0) g_cnt = 0;
}

// ------------------------------ main kernel --------------------------------
__global__ void __launch_bounds__(THR, 1)
main_kernel(const float* __restrict__ projW,
            const float* __restrict__ projb,
            float* __restrict__ out) {
    extern __shared__ char dsm_raw[];
    const uint32_t raw32 = smem_u32(dsm_raw);
    const uint32_t dsm32 = (raw32 + 1023u) & ~1023u;

    const int tid  = threadIdx.x;
    const int lane = tid & 31;
    const int w    = tid >> 5;         // 0..15
    const int wm   = w & 3;            // M slice (16 rows)
    const int wn   = w >> 2;           // N slice (16 cols)
    const int bid  = blockIdx.x;       // 128 CTAs: 4M x 32N
    const int mT   = bid >> 5;
    const int nT   = bid & 31;
    const int bm   = mT * 64;
    const int colb = nT * 64;
    const int G16  = nT * 4 + wn;      // 16-col block = 4 units x 4 gates

    // Precompute swizzled LDSM offsets (stage-relative); hot loop is IADD-only.
    uint32_t asw[4], bsw[4];
    {
        const int abase = (wm * 16 + (lane & 15)) * 128 + ((lane >> 4) << 4);
        const int bbase = (wn * 16 + (lane & 7) + ((lane >> 4) << 3)) * 128
                        + (((lane >> 3) & 1) << 4);
#pragma unroll
        for (int ka = 0; ka < 4; ++ka) {
            const int ao = abase + ka * 32;
            asw[ka] = ao ^ ((ao >> 3) & 0x70);
            const int bo = bbase + ka * 32;
            bsw[ka] = OFF_B + (bo ^ ((bo >> 3) & 0x70));
        }
    }

    float accA[2][4], accB[2][4];
    float c0[2], c1[2];
    c0[0] = c0[1] = c1[0] = c1[1] = 0.0f;

    Seg segs[4];
    unsigned gsv = 0;

    // ------------- superstep s = 0: x0 chunk only, no prior barrier --------
    ZERO_ACC(accA);
    chunk0_x0(dsm32, g_xc, accA, bm, colb, tid, asw, bsw);
    epilogue_lstm(accA, c0, g_b0, nullptr, nullptr,
                  g_hs, nullptr, nullptr, bm, G16, wm, lane);
    arrive_gs(gsv);

    // -------- fused encoder wavefront: superstep s = enc0(s) + enc1(s-1) ----
    for (int s = 1; s <= T_IN; ++s) {
        ZERO_ACC(accA); ZERO_ACC(accB);
        // barrier-independent x0 chunk overlaps the barrier release
        if (s < T_IN)
            chunk0_x0(dsm32, g_xc + (size_t)s * Bsz * Fin, accA, bm, colb, tid, asw, bsw);
        wait_gs(gsv);

        int ns = 0, split = 0;
        if (s < T_IN) { segs[ns++] = { g_hs + (size_t)(s - 1) * BH, gB_h0, Hd }; split = 8; }
        segs[ns++] = { g_hs + (size_t)(s - 1) * BH, gB_x1, Hd };
        if (s >= 2) segs[ns++] = { &g_h1[s & 1][0], gB_h1, Hd };

        pipe_gemm(dsm32, segs, ns, split, accA, accB, bm, colb, tid, asw, bsw);
        if (s < T_IN)
            epilogue_lstm(accA, c0, g_b0, nullptr, nullptr,
                          g_hs + (size_t)s * BH, nullptr, nullptr, bm, G16, wm, lane);
        epilogue_lstm(accB, c1, g_b1, nullptr, nullptr,
                      &g_h1[(s - 1) & 1][0], nullptr, nullptr, bm, G16, wm, lane);
        arrive_gs(gsv);
    }

    // -------------------------------- decoder -------------------------------
    const f16 *h0p = g_hs + (size_t)(T_IN - 1) * BH;
    const f16 *h1p = &g_h1[(T_IN - 1) & 1][0];
    const float pjb = projb[0];

    for (int t = 0; t < T_OUT; ++t) {
        // phase A: dec0(t)
        wait_gs(gsv);
        if (bid == 0 && tid < Bsz && t >= 1)
            out[(size_t)tid * T_OUT + (t - 1)] = g_pacc[t & 1][tid];
        if (bid == 1 && tid < Bsz)
            g_pacc[(t + 1) & 1][tid] = pjb;

        segs[0] = { h0p, gB_d0, Hd };
        ZERO_ACC(accA);
        pipe_gemm(dsm32, segs, 1, 8, accA, accA, bm, colb, tid, asw, bsw);
        epilogue_lstm(accA, c0, g_bd0, &g_pacc[t & 1][0], g_Wv,
                      &g_d0[t & 1][0], nullptr, nullptr, bm, G16, wm, lane);
        arrive_gs(gsv);

        // phase B: dec1(t) + fused projection into pacc[(t+1)&1]
        wait_gs(gsv);
        segs[0] = { &g_d0[t & 1][0], gB_x1d, Hd };
        segs[1] = { h1p, gB_d1, Hd };
        ZERO_ACC(accA);
        pipe_gemm(dsm32, segs, 2, 16, accA, accA, bm, colb, tid, asw, bsw);
        epilogue_lstm(accA, c1, g_bd1, nullptr, nullptr,
                      &g_d1[t & 1][0], projW, &g_pacc[(t + 1) & 1][0],
                      bm, G16, wm, lane);
        arrive_gs(gsv);

        h0p = &g_d0[t & 1][0];
        h1p = &g_d1[t & 1][0];
    }

    // final output column (t = 63): slot (63+1)&1 = 0
    wait_gs(gsv);
    if (bid == 0 && tid < Bsz)
        out[(size_t)tid * T_OUT + (T_OUT - 1)] = g_pacc[0][tid];
}

// ------------------------------- host side ---------------------------------
extern "C" void kernel_launch(void* const* d_in, const int* in_sizes, int n_in,
                              void* d_out, int out_size) {
    const float* x      = (const float*)d_in[0];
    const float* e0Wih  = (const float*)d_in[2];
    const float* e0Whh  = (const float*)d_in[3];
    const float* e0bih  = (const float*)d_in[4];
    const float* e0bhh  = (const float*)d_in[5];
    const float* e1Wih  = (const float*)d_in[6];
    const float* e1Whh  = (const float*)d_in[7];
    const float* e1bih  = (const float*)d_in[8];
    const float* e1bhh  = (const float*)d_in[9];
    const float* d0Wih  = (const float*)d_in[10];
    const float* d0Whh  = (const float*)d_in[11];
    const float* d0bih  = (const float*)d_in[12];
    const float* d0bhh  = (const float*)d_in[13];
    const float* d1Wih  = (const float*)d_in[14];
    const float* d1Whh  = (const float*)d_in[15];
    const float* d1bih  = (const float*)d_in[16];
    const float* d1bhh  = (const float*)d_in[17];
    const float* projW  = (const float*)d_in[18];
    const float* projb  = (const float*)d_in[19];
    float* out = (float*)d_out;

    const long long total = 6LL * N4 * Hd + (long long)N4 * Fin
                          + (long long)Bsz * T_IN * Fin + N4 + Bsz + 1;
    const int nblk = (int)((total + 255) / 256);
    prep_kernel<<<nblk, 256>>>(x,
        e0Wih, e0Whh, e0bih, e0bhh,
        e1Wih, e1Whh, e1bih, e1bhh,
        d0Wih, d0Whh, d0bih, d0bhh,
        d1Wih, d1Whh, d1bih, d1bhh, projb);

    cudaFuncSetAttribute(main_kernel, cudaFuncAttributeMaxDynamicSharedMemorySize, DSMEM);
    main_kernel<<<NBLK, THR, DSMEM>>>(projW, projb, out);
}

// round 17
// speedup vs baseline: 1.4442x; 1.3118x over previous
#include <cuda_runtime.h>
#include <cuda_fp16.h>
#include <cstdint>
#include <math.h>

// ---------------------------------------------------------------------------
// Seq2Seq LSTM via mma.sync (HMMA fp16): B=256, T_in=512, F=64, H=512, T_out=64
// Round 17: COMPILE-TIME pipeline specialization. pipe_fixed<NCH,SPLIT> fully
// unrolls the quad-group pipeline (NCH = 24/16/8 chunks), so stage addresses
// become immediates, segment selection constant-folds, and all cursor/wrap/
// bound bookkeeping disappears. Per-thread A/B row offsets hoisted to kernel
// top. Everything else = round-16 champion (split-phase grid barrier with x0
// overlap, 128 CTAs, 512 thr, 16x16 warp tiles, fast-math epilogue).
// ---------------------------------------------------------------------------

using f16 = __half;

#define Bsz   256
#define Hd    512
#define Fin   64
#define T_IN  512
#define T_OUT 64
#define N4    2048
#define BH    (Bsz*Hd)
#define NBLK  128
#define THR   512

// per-stage smem: A 8K | B 8K
#define OFF_B  8192
#define BUFB   16384
#define NSTAGE 12
#define DSMEM  (NSTAGE*BUFB + 1024)

// ------------------------- device scratch (static) -------------------------
__device__ __align__(16) f16 g_xc[(size_t)T_IN * Bsz * Fin];
__device__ __align__(16) f16 g_hs[(size_t)T_IN * BH];
__device__ __align__(16) f16 g_h1[2][BH];
__device__ __align__(16) f16 g_d0[2][BH];
__device__ __align__(16) f16 g_d1[2][BH];
__device__ float g_pacc[2][Bsz];          // proj ping-pong accumulators

// weights, remapped rows (see remap_row), layout [2048][K] fp16
__device__ __align__(16) f16 gB_x0[N4 * Fin];
__device__ __align__(16) f16 gB_h0[N4 * Hd];
__device__ __align__(16) f16 gB_x1[N4 * Hd];
__device__ __align__(16) f16 gB_h1[N4 * Hd];
__device__ __align__(16) f16 gB_d0[N4 * Hd];
__device__ __align__(16) f16 gB_x1d[N4 * Hd];
__device__ __align__(16) f16 gB_d1[N4 * Hd];

__device__ __align__(16) float g_b0[N4], g_b1[N4], g_bd0[N4], g_bd1[N4], g_Wv[N4];

__device__ unsigned g_cnt;
__device__ volatile unsigned g_gen;

// ------------------------------- asm helpers -------------------------------
#define LDSM4(R, A) \
    asm volatile("ldmatrix.sync.aligned.m8n8.x4.shared.b16 {%0,%1,%2,%3}, [%4];" \
        : "=r"((R)[0]), "=r"((R)[1]), "=r"((R)[2]), "=r"((R)[3]) : "r"(A))

#define MMA(D, A, B) \
    asm volatile("mma.sync.aligned.m16n8k16.row.col.f32.f16.f16.f32 " \
        "{%0,%1,%2,%3}, {%4,%5,%6,%7}, {%8,%9}, {%0,%1,%2,%3};" \
        : "+f"((D)[0]), "+f"((D)[1]), "+f"((D)[2]), "+f"((D)[3]) \
        : "r"((A)[0]), "r"((A)[1]), "r"((A)[2]), "r"((A)[3]), \
          "r"((B)[0]), "r"((B)[1]))

#define CP16(sa, ga) \
    asm volatile("cp.async.cg.shared.global [%0], [%1], 16;" :: "r"(sa), "l"(ga))
#define CP_COMMIT() asm volatile("cp.async.commit_group;")
#define CP_WAIT0()  asm volatile("cp.async.wait_group 0;" ::: "memory")
#define CP_WAIT1()  asm volatile("cp.async.wait_group 1;" ::: "memory")

__device__ __forceinline__ uint32_t smem_u32(const void* p) {
    uint32_t a;
    asm("{ .reg .u64 t; cvta.to.shared.u64 t, %1; cvt.u32.u64 %0, t; }"
        : "=r"(a) : "l"(p));
    return a;
}

// Fast activations: MUFU-based. |err| ~2^-21, far below fp16 gate noise.
__device__ __forceinline__ float sigf(float x) {
    return __fdividef(1.0f, 1.0f + __expf(-x));
}
__device__ __forceinline__ float tanhf_fast(float x) {
    return 1.0f - __fdividef(2.0f, __expf(2.0f * x) + 1.0f);
}

// ---- split-phase grid barrier (sense = generation counter) ----
__device__ __forceinline__ void arrive_gs(unsigned& mygen) {
    __syncthreads();
    if (threadIdx.x == 0) {
        __threadfence();
        unsigned g = g_gen;
        mygen = g;
        unsigned old = atomicAdd(&g_cnt, 1u);
        if (old == NBLK - 1) {
            g_cnt = 0;
            __threadfence();
            g_gen = g + 1;
        }
    }
}
__device__ __forceinline__ void wait_gs(unsigned mygen) {
    if (threadIdx.x == 0) {
        while (g_gen == mygen) __nanosleep(32);
        __threadfence();
    }
    __syncthreads();
}

// ----------------------------- GEMM machinery ------------------------------
// Warp tile 16x16, single pass fp16; all LDSM offsets precomputed.
__device__ __forceinline__ void compute_chunk(uint32_t sbase, float acc[2][4],
                                              const uint32_t* asw,
                                              const uint32_t* bsw) {
#pragma unroll
    for (int ka = 0; ka < 4; ++ka) {
        uint32_t a[4], b[4];
        LDSM4(a, sbase + asw[ka]);
        LDSM4(b, sbase + bsw[ka]);
        MMA(acc[0], a, b);
        MMA(acc[1], a, b + 2);
    }
}

// Barrier-independent x0 chunk: A = x_t slice, B = Wx0 (both static).
__device__ __forceinline__ void chunk0_x0(uint32_t dsm32, const f16* Ax,
                                          const f16* Bx,
                                          float acc[2][4], uint32_t swA,
                                          const uint32_t* asw,
                                          const uint32_t* bsw) {
    CP16(dsm32 + swA, Ax);
    CP16(dsm32 + OFF_B + swA, Bx);
    CP_COMMIT();
    CP_WAIT0();
    __syncthreads();
    compute_chunk(dsm32, acc, asw, bsw);
    __syncthreads();                 // stage 0 free for the pipeline prefill
}

// Fully-unrolled quad-group pipeline. NCH chunks (all K=512, segment = c>>3),
// chunks < SPLIT accumulate into accA, rest into accB. Stage = c % NSTAGE
// (compile-time). A/B pointers pre-offset by the thread's row offset.
template <int NCH, int SPLIT>
__device__ __forceinline__ void pipe_fixed(
    uint32_t dsm32, uint32_t swA, uint32_t swB,
    const f16* A0, const f16* B0,
    const f16* A1, const f16* B1,
    const f16* A2, const f16* B2,
    float accA[2][4], float accB[2][4],
    const uint32_t* asw, const uint32_t* bsw) {
    const f16* As[3] = { A0, A1, A2 };
    const f16* Bs[3] = { B0, B1, B2 };
    constexpr int G = NCH / 4;

    // prefill 2 groups (or all, if fewer)
#pragma unroll
    for (int c = 0; c < (NCH < 8 ? NCH : 8); ++c) {
        const uint32_t st = dsm32 + (c % NSTAGE) * BUFB;
        CP16(st + swA, As[c >> 3] + (c & 7) * 64);
        CP16(st + swB, Bs[c >> 3] + (c & 7) * 64);
        if ((c & 3) == 3) CP_COMMIT();
    }
#pragma unroll
    for (int g = 0; g < G; ++g) {
        if (g + 1 < G) CP_WAIT1();
        else           CP_WAIT0();
        __syncthreads();
        if (g + 2 < G) {
#pragma unroll
            for (int j = 0; j < 4; ++j) {
                const int c = 4 * (g + 2) + j;
                const uint32_t st = dsm32 + (c % NSTAGE) * BUFB;
                CP16(st + swA, As[c >> 3] + (c & 7) * 64);
                CP16(st + swB, Bs[c >> 3] + (c & 7) * 64);
            }
            CP_COMMIT();
        }
#pragma unroll
        for (int j = 0; j < 4; ++j) {
            const int c = 4 * g + j;
            const uint32_t cb = dsm32 + (c % NSTAGE) * BUFB;
            compute_chunk(cb, (c < SPLIT) ? accA : accB, asw, bsw);
        }
    }
}

#define ZERO_ACC(A) \
    do { _Pragma("unroll") for (int _a = 0; _a < 2; ++_a) \
         _Pragma("unroll") for (int _d = 0; _d < 4; ++_d) (A)[_a][_d] = 0.0f; } while (0)

// Epilogue: thread owns rows {m, m+8} x ONE unit (all 4 gates).
__device__ __forceinline__ void epilogue_lstm(float acc[2][4], float* c,
                                              const float* bias,
                                              const float* prevv, const float* Wv,
                                              f16* H,
                                              const float* pjW, float* pacc,
                                              int bm, int G16, int wm, int lane) {
    const int q = lane & 3, r = lane >> 2;
    const float2* b2 = (const float2*)bias;
    const float2 bIF = __ldg(&b2[G16 * 8 + q]);
    const float2 bGO = __ldg(&b2[G16 * 8 + 4 + q]);
    float2 wIF = make_float2(0.f, 0.f), wGO = make_float2(0.f, 0.f);
    if (Wv) {
        const float2* w2 = (const float2*)Wv;
        wIF = __ldg(&w2[G16 * 8 + q]);
        wGO = __ldg(&w2[G16 * 8 + 4 + q]);
    }
    const int u = G16 * 4 + q;
    float pw = 0.0f;
    if (pjW) pw = __ldg(&pjW[u]);
    float rsum[2] = {0.0f, 0.0f};
#pragma unroll
    for (int rr = 0; rr < 2; ++rr) {
        const int m = bm + wm * 16 + r + rr * 8;
        float gi = acc[0][rr * 2 + 0] + bIF.x;
        float gf = acc[0][rr * 2 + 1] + bIF.y;
        float gg = acc[1][rr * 2 + 0] + bGO.x;
        float go = acc[1][rr * 2 + 1] + bGO.y;
        if (prevv) {
            const float pv = prevv[m];
            gi = fmaf(pv, wIF.x, gi); gf = fmaf(pv, wIF.y, gf);
            gg = fmaf(pv, wGO.x, gg); go = fmaf(pv, wGO.y, go);
        }
        float cn = sigf(gf) * c[rr] + sigf(gi) * tanhf_fast(gg);
        float hn = sigf(go) * tanhf_fast(cn);
        c[rr] = cn;
        if (pjW) rsum[rr] = hn * pw;
        H[(size_t)m * Hd + u] = __float2half(hn);
    }
    if (pjW) {
#pragma unroll
        for (int rr = 0; rr < 2; ++rr) {
            rsum[rr] += __shfl_xor_sync(0xffffffffu, rsum[rr], 1);
            rsum[rr] += __shfl_xor_sync(0xffffffffu, rsum[rr], 2);
        }
        if (q == 0) {
            atomicAdd(&pacc[bm + wm * 16 + r], rsum[0]);
            atomicAdd(&pacc[bm + wm * 16 + r + 8], rsum[1]);
        }
    }
}

// ------------------------------- prep kernel -------------------------------
// gate g (0..3), unit j (0..511) -> col = 16*(j>>2) + 2*(j&3) + (g&1) + 8*(g>>1)
__device__ __forceinline__ int remap_row(int r) {
    const int g = r >> 9, j = r & 511;
    return ((j >> 2) << 4) + ((j & 3) << 1) + (g & 1) + ((g >> 1) << 3);
}

__global__ void prep_kernel(
    const float* __restrict__ x,
    const float* __restrict__ e0Wih, const float* __restrict__ e0Whh,
    const float* __restrict__ e0bih, const float* __restrict__ e0bhh,
    const float* __restrict__ e1Wih, const float* __restrict__ e1Whh,
    const float* __restrict__ e1bih, const float* __restrict__ e1bhh,
    const float* __restrict__ d0Wih, const float* __restrict__ d0Whh,
    const float* __restrict__ d0bih, const float* __restrict__ d0bhh,
    const float* __restrict__ d1Wih, const float* __restrict__ d1Whh,
    const float* __restrict__ d1bih, const float* __restrict__ d1bhh,
    const float* __restrict__ projb) {
    const size_t FULL = (size_t)N4 * Hd;
    long long idx = (long long)blockIdx.x * 256 + threadIdx.x;

    if (idx < (long long)(6 * FULL)) {
        int seg = (int)(idx / FULL);
        size_t i = (size_t)(idx % FULL);
        int r = (int)(i / Hd), k = (int)(i % Hd);
        size_t dst = (size_t)remap_row(r) * Hd + k;
        const float* src; f16* d;
        switch (seg) {
            case 0: src = e0Whh; d = gB_h0;  break;
            case 1: src = e1Wih; d = gB_x1;  break;
            case 2: src = e1Whh; d = gB_h1;  break;
            case 3: src = d0Whh; d = gB_d0;  break;
            case 4: src = d1Wih; d = gB_x1d; break;
            default: src = d1Whh; d = gB_d1; break;
        }
        d[dst] = __float2half(src[i]);
        return;
    }
    idx -= 6LL * FULL;

    if (idx < (long long)N4 * Fin) {   // Wx0
        size_t i = (size_t)idx;
        int r = (int)(i / Fin), k = (int)(i % Fin);
        gB_x0[(size_t)remap_row(r) * Fin + k] = __float2half(e0Wih[i]);
        return;
    }
    idx -= (long long)N4 * Fin;

    if (idx < (long long)Bsz * T_IN * Fin) {   // x -> [t][b][f]
        size_t i = (size_t)idx;
        int b = (int)(i / (T_IN * Fin));
        int t = (int)((i / Fin) % T_IN);
        int f = (int)(i % Fin);
        g_xc[(size_t)t * Bsz * Fin + b * Fin + f] = __float2half(x[i]);
        return;
    }
    idx -= (long long)Bsz * T_IN * Fin;

    if (idx < N4) {                    // biases + Wv, remapped (fp32)
        int r = (int)idx;
        int dst = remap_row(r);
        g_Wv[dst]  = d0Wih[r];
        g_b0[dst]  = e0bih[r] + e0bhh[r];
        g_b1[dst]  = e1bih[r] + e1bhh[r];
        g_bd0[dst] = d0bih[r] + d0bhh[r];
        g_bd1[dst] = d1bih[r] + d1bhh[r];
        return;
    }
    idx -= N4;

    if (idx < Bsz) {                   // prev slot0 = x[:, -1, -1]; slot1 = projb
        g_pacc[0][idx] = x[(size_t)(idx + 1) * T_IN * Fin - 1];
        g_pacc[1][idx] = projb[0];
        return;
    }
    idx -= Bsz;
    if (idx == 0) g_cnt = 0;
}

// ------------------------------ main kernel --------------------------------
__global__ void __launch_bounds__(THR, 1)
main_kernel(const float* __restrict__ projW,
            const float* __restrict__ projb,
            float* __restrict__ out) {
    extern __shared__ char dsm_raw[];
    const uint32_t raw32 = smem_u32(dsm_raw);
    const uint32_t dsm32 = (raw32 + 1023u) & ~1023u;

    const int tid  = threadIdx.x;
    const int lane = tid & 31;
    const int w    = tid >> 5;         // 0..15
    const int wm   = w & 3;            // M slice (16 rows)
    const int wn   = w >> 2;           // N slice (16 cols)
    const int bid  = blockIdx.x;       // 128 CTAs: 4M x 32N
    const int mT   = bid >> 5;
    const int nT   = bid & 31;
    const int bm   = mT * 64;
    const int colb = nT * 64;
    const int G16  = nT * 4 + wn;      // 16-col block = 4 units x 4 gates

    // Precomputed swizzled LDSM offsets (stage-relative).
    uint32_t asw[4], bsw[4];
    {
        const int abase = (wm * 16 + (lane & 15)) * 128 + ((lane >> 4) << 4);
        const int bbase = (wn * 16 + (lane & 7) + ((lane >> 4) << 3)) * 128
                        + (((lane >> 3) & 1) << 4);
#pragma unroll
        for (int ka = 0; ka < 4; ++ka) {
            const int ao = abase + ka * 32;
            asw[ka] = ao ^ ((ao >> 3) & 0x70);
            const int bo = bbase + ka * 32;
            bsw[ka] = OFF_B + (bo ^ ((bo >> 3) & 0x70));
        }
    }

    // Per-thread cp.async offsets (loop-invariant across all supersteps).
    const int row = tid >> 3, sg8 = (tid & 7) * 8;
    const uint32_t swA = (uint32_t)((tid * 16) ^ (((tid * 16) >> 3) & 0x70));
    const uint32_t swB = swA + OFF_B;
    const int raOff = (bm + row) * 512 + sg8;     // A row offset, K=512
    const int rbOff = (colb + row) * 512 + sg8;   // B row offset, K=512
    const int ra64  = (bm + row) * 64 + sg8;      // A row offset, K=64
    const int rb64  = (colb + row) * 64 + sg8;

    float accA[2][4], accB[2][4];
    float c0[2], c1[2];
    c0[0] = c0[1] = c1[0] = c1[1] = 0.0f;
    unsigned gsv = 0;

    // ------------- superstep s = 0: x0 chunk only, no prior barrier --------
    ZERO_ACC(accA);
    chunk0_x0(dsm32, g_xc + ra64, gB_x0 + rb64, accA, swA, asw, bsw);
    epilogue_lstm(accA, c0, g_b0, nullptr, nullptr,
                  g_hs, nullptr, nullptr, bm, G16, wm, lane);
    arrive_gs(gsv);

    // -------- fused encoder wavefront: superstep s = enc0(s) + enc1(s-1) ----
    for (int s = 1; s <= T_IN; ++s) {
        ZERO_ACC(accA); ZERO_ACC(accB);
        if (s < T_IN)
            chunk0_x0(dsm32, g_xc + (size_t)s * Bsz * Fin + ra64, gB_x0 + rb64,
                      accA, swA, asw, bsw);
        wait_gs(gsv);

        const f16* hp = g_hs + (size_t)(s - 1) * BH + raOff;
        const f16* h1p = &g_h1[s & 1][0] + raOff;
        if (s >= 2 && s < T_IN) {
            pipe_fixed<24, 8>(dsm32, swA, swB,
                              hp, gB_h0 + rbOff,
                              hp, gB_x1 + rbOff,
                              h1p, gB_h1 + rbOff,
                              accA, accB, asw, bsw);
        } else if (s == 1) {
            pipe_fixed<16, 8>(dsm32, swA, swB,
                              hp, gB_h0 + rbOff,
                              hp, gB_x1 + rbOff,
                              hp, gB_x1 + rbOff,
                              accA, accB, asw, bsw);
        } else {  // s == T_IN: enc1 only (x1 + h1)
            pipe_fixed<16, 0>(dsm32, swA, swB,
                              hp, gB_x1 + rbOff,
                              h1p, gB_h1 + rbOff,
                              h1p, gB_h1 + rbOff,
                              accA, accB, asw, bsw);
        }
        if (s < T_IN)
            epilogue_lstm(accA, c0, g_b0, nullptr, nullptr,
                          g_hs + (size_t)s * BH, nullptr, nullptr, bm, G16, wm, lane);
        epilogue_lstm(accB, c1, g_b1, nullptr, nullptr,
                      &g_h1[(s - 1) & 1][0], nullptr, nullptr, bm, G16, wm, lane);
        arrive_gs(gsv);
    }

    // -------------------------------- decoder -------------------------------
    const f16 *h0p = g_hs + (size_t)(T_IN - 1) * BH;
    const f16 *h1p = &g_h1[(T_IN - 1) & 1][0];
    const float pjb = projb[0];

    for (int t = 0; t < T_OUT; ++t) {
        // phase A: dec0(t)
        wait_gs(gsv);
        if (bid == 0 && tid < Bsz && t >= 1)
            out[(size_t)tid * T_OUT + (t - 1)] = g_pacc[t & 1][tid];
        if (bid == 1 && tid < Bsz)
            g_pacc[(t + 1) & 1][tid] = pjb;

        ZERO_ACC(accA);
        pipe_fixed<8, 8>(dsm32, swA, swB,
                         h0p + raOff, gB_d0 + rbOff,
                         h0p + raOff, gB_d0 + rbOff,
                         h0p + raOff, gB_d0 + rbOff,
                         accA, accA, asw, bsw);
        epilogue_lstm(accA, c0, g_bd0, &g_pacc[t & 1][0], g_Wv,
                      &g_d0[t & 1][0], nullptr, nullptr, bm, G16, wm, lane);
        arrive_gs(gsv);

        // phase B: dec1(t) + fused projection into pacc[(t+1)&1]
        wait_gs(gsv);
        ZERO_ACC(accA);
        pipe_fixed<16, 16>(dsm32, swA, swB,
                           &g_d0[t & 1][0] + raOff, gB_x1d + rbOff,
                           h1p + raOff, gB_d1 + rbOff,
                           h1p + raOff, gB_d1 + rbOff,
                           accA, accA, asw, bsw);
        epilogue_lstm(accA, c1, g_bd1, nullptr, nullptr,
                      &g_d1[t & 1][0], projW, &g_pacc[(t + 1) & 1][0],
                      bm, G16, wm, lane);
        arrive_gs(gsv);

        h0p = &g_d0[t & 1][0];
        h1p = &g_d1[t & 1][0];
    }

    // final output column (t = 63): slot (63+1)&1 = 0
    wait_gs(gsv);
    if (bid == 0 && tid < Bsz)
        out[(size_t)tid * T_OUT + (T_OUT - 1)] = g_pacc[0][tid];
}

// ------------------------------- host side ---------------------------------
extern "C" void kernel_launch(void* const* d_in, const int* in_sizes, int n_in,
                              void* d_out, int out_size) {
    const float* x      = (const float*)d_in[0];
    const float* e0Wih  = (const float*)d_in[2];
    const float* e0Whh  = (const float*)d_in[3];
    const float* e0bih  = (const float*)d_in[4];
    const float* e0bhh  = (const float*)d_in[5];
    const float* e1Wih  = (const float*)d_in[6];
    const float* e1Whh  = (const float*)d_in[7];
    const float* e1bih  = (const float*)d_in[8];
    const float* e1bhh  = (const float*)d_in[9];
    const float* d0Wih  = (const float*)d_in[10];
    const float* d0Whh  = (const float*)d_in[11];
    const float* d0bih  = (const float*)d_in[12];
    const float* d0bhh  = (const float*)d_in[13];
    const float* d1Wih  = (const float*)d_in[14];
    const float* d1Whh  = (const float*)d_in[15];
    const float* d1bih  = (const float*)d_in[16];
    const float* d1bhh  = (const float*)d_in[17];
    const float* projW  = (const float*)d_in[18];
    const float* projb  = (const float*)d_in[19];
    float* out = (float*)d_out;

    const long long total = 6LL * N4 * Hd + (long long)N4 * Fin
                          + (long long)Bsz * T_IN * Fin + N4 + Bsz + 1;
    const int nblk = (int)((total + 255) / 256);
    prep_kernel<<<nblk, 256>>>(x,
        e0Wih, e0Whh, e0bih, e0bhh,
        e1Wih, e1Whh, e1bih, e1bhh,
        d0Wih, d0Whh, d0bih, d0bhh,
        d1Wih, d1Whh, d1bih, d1bhh, projb);

    cudaFuncSetAttribute(main_kernel, cudaFuncAttributeMaxDynamicSharedMemorySize, DSMEM);
    main_kernel<<<NBLK, THR, DSMEM>>>(projW, projb, out);
}